// round 15
// baseline (speedup 1.0000x reference)
#include <cuda_runtime.h>
#include <cstdint>

#define NB   16
#define NC   21
#define ND   512
#define HW   4096
#define NR   (NB*NC)   /* 336 */
#define RP   384
#define LABW 513
#define KSPL 16        /* K=32 per GEMM task */
#define NTRI 21        /* lower-tri 64x64 tiles of 6x6 */
#define NTASK (KSPL*NTRI)  /* 336 */

// -------- device scratch (no allocations allowed) --------
__device__ unsigned char g_lab[NB * HW];        // resized labels, u8
__device__ int           g_cntC[NB * 32][NC];   // per-chunk class counts
__device__ float         g_sums[RP * ND];       // pooled sums (rows >=336 never
                                                // written -> stay zero forever)
__device__ float         g_S[RP * RP];          // raw Gram (atomic; lower tiles)

// ============================================================
// K1: bilinear label resize (jax bilinear, antialias=False, fp32,
// H then W, truncation). Scattered independent loads (MLP 4),
// grid (16 images, 32 slabs) x 128 thr, 1 px/thread. Also zeroes
// g_S (graph-ordered before k4) and d_out.
// ============================================================
__global__ __launch_bounds__(128) void k1_labels(const int* __restrict__ labels,
                                                 float* __restrict__ out)
{
    int b = blockIdx.x, j = blockIdx.y;
    int tid = threadIdx.x;
    __shared__ int scnt[NC];
    if (tid < NC) scnt[tid] = 0;

    // zero g_S: 36864 float4 spread over 65536 threads
    int gt = (j * NB + b) * 128 + tid;
    if (gt < RP * RP / 4)
        ((float4*)g_S)[gt] = make_float4(0.f, 0.f, 0.f, 0.f);
    __syncthreads();

    const int* lb = labels + (size_t)b * (LABW * LABW);
    int o  = j * 128 + tid;
    int oy = o >> 6, ox = o & 63;

    float sy  = __fsub_rn(__fmul_rn((float)oy + 0.5f, 8.015625f), 0.5f);
    int   y0  = (int)floorf(sy);
    float fy  = __fsub_rn(sy, (float)y0);
    float wy0 = __fsub_rn(1.0f, fy);
    float xy1 = __fsub_rn((float)(y0 + 1), sy);
    float wy1 = __fsub_rn(1.0f, xy1);
    float ty  = __fadd_rn(wy0, wy1);
    wy0 = __fdiv_rn(wy0, ty);
    wy1 = __fdiv_rn(wy1, ty);

    float sx  = __fsub_rn(__fmul_rn((float)ox + 0.5f, 8.015625f), 0.5f);
    int   x0  = (int)floorf(sx);
    float fx  = __fsub_rn(sx, (float)x0);
    float wx0 = __fsub_rn(1.0f, fx);
    float xx1 = __fsub_rn((float)(x0 + 1), sx);
    float wx1 = __fsub_rn(1.0f, xx1);
    float tx  = __fadd_rn(wx0, wx1);
    wx0 = __fdiv_rn(wx0, tx);
    wx1 = __fdiv_rn(wx1, tx);

    float v00 = (float)lb[y0 * LABW + x0];
    float v01 = (float)lb[y0 * LABW + x0 + 1];
    float v10 = (float)lb[(y0 + 1) * LABW + x0];
    float v11 = (float)lb[(y0 + 1) * LABW + x0 + 1];

    float t0 = __fadd_rn(__fmul_rn(wy0, v00), __fmul_rn(wy1, v10));
    float t1 = __fadd_rn(__fmul_rn(wy0, v01), __fmul_rn(wy1, v11));
    float v  = __fadd_rn(__fmul_rn(wx0, t0), __fmul_rn(wx1, t1));

    int li = (int)v;   // truncation toward zero (values >= 0)
    g_lab[b * HW + o] = (unsigned char)li;
    atomicAdd(&scnt[li], 1);
    __syncthreads();
    if (tid < NC) g_cntC[b * 32 + j][tid] = scnt[tid];
    if (b == 0 && j == 0 && tid == 0) out[0] = 0.0f;
}

// ============================================================
// K2: masked pooling (128MB DRAM pass). 2048 blocks x 128 thr,
// FOUR d-channels per block: labels loaded ONCE into registers
// and reused across the 4 feature passes (label L2 traffic /4).
// Conflict-free smem scatter (bank = tid%32 for all classes).
// ============================================================
__global__ __launch_bounds__(128) void k2_pool(const float* __restrict__ feat)
{
    __shared__ float sacc[NC * 128];
    int tid = threadIdx.x;
    int blk = blockIdx.x;          // 128 blocks per image
    int b   = blk >> 7;
    int d0  = (blk & 127) * 4;

    const unsigned int* l4 = (const unsigned int*)g_lab + b * (HW / 4);
    unsigned int lv[8];
#pragma unroll
    for (int k = 0; k < 8; k++) lv[k] = l4[tid + 128 * k];

    for (int dd = 0; dd < 4; dd++) {
        int bd = b * ND + d0 + dd;

        float4* z4 = (float4*)sacc;
#pragma unroll
        for (int i = 0; i < 6; i++) {
            int idx = tid + 128 * i;
            if (idx < NC * 32) z4[idx] = make_float4(0.f, 0.f, 0.f, 0.f);
        }
        __syncthreads();

        const float4* f4 = (const float4*)(feat + (size_t)bd * HW);
        float4 fv[8];
#pragma unroll
        for (int k = 0; k < 8; k++) fv[k] = f4[tid + 128 * k];

#pragma unroll
        for (int k = 0; k < 8; k++) {
            unsigned int L = lv[k];
            sacc[((L      ) & 255u) * 128 + tid] += fv[k].x;
            sacc[((L >>  8) & 255u) * 128 + tid] += fv[k].y;
            sacc[((L >> 16) & 255u) * 128 + tid] += fv[k].z;
            sacc[((L >> 24) & 255u) * 128 + tid] += fv[k].w;
        }
        __syncthreads();

        int w = tid >> 5, l = tid & 31;
        for (int c = w; c < NC; c += 4) {
            const float* p = &sacc[c * 128 + l];
            float s = p[0] + p[32] + p[64] + p[96];
#pragma unroll
            for (int o = 16; o; o >>= 1) s += __shfl_xor_sync(0xffffffffu, s, o);
            if (l == 0)
                g_sums[(size_t)(b * NC + c) * ND + d0 + dd] = s;
        }
        __syncthreads();
    }
}

// ============================================================
// K4: RAW Gram (unnormalized sums), lower-tri 64x64 tiles,
// K=32 per block, ONE task per block (336 blocks, single wave),
// all 4 tile-loads prefetched, atomicAdd accumulation into g_S
// (zeroed by k1). Normalization deferred to k5 via the diagonal.
// ============================================================
__global__ __launch_bounds__(256) void k4_gemm()
{
    __shared__ float As[2][16][68];
    __shared__ float Bs[2][16][68];
    int tid = threadIdx.x;
    int bid = blockIdx.x;
    int z = bid / NTRI, t = bid - z * NTRI;

    int ti = 0;
    while ((ti + 1) * (ti + 2) / 2 <= t) ti++;
    int tj = t - ti * (ti + 1) / 2;

    int m0 = ti * 64, n0 = tj * 64, k0 = z * 32;
    int tx = tid & 15, ty = tid >> 4;
    int lr = tid >> 2, lq = tid & 3;

    const float* pa = &g_sums[(size_t)(m0 + lr) * ND + k0 + lq * 4];
    const float* pb = &g_sums[(size_t)(n0 + lr) * ND + k0 + lq * 4];
    float4 av0 = *(const float4*)pa;
    float4 bv0 = *(const float4*)pb;
    float4 av1 = *(const float4*)(pa + 16);
    float4 bv1 = *(const float4*)(pb + 16);

    As[0][lq * 4 + 0][lr] = av0.x; As[0][lq * 4 + 1][lr] = av0.y;
    As[0][lq * 4 + 2][lr] = av0.z; As[0][lq * 4 + 3][lr] = av0.w;
    Bs[0][lq * 4 + 0][lr] = bv0.x; Bs[0][lq * 4 + 1][lr] = bv0.y;
    Bs[0][lq * 4 + 2][lr] = bv0.z; Bs[0][lq * 4 + 3][lr] = bv0.w;
    As[1][lq * 4 + 0][lr] = av1.x; As[1][lq * 4 + 1][lr] = av1.y;
    As[1][lq * 4 + 2][lr] = av1.z; As[1][lq * 4 + 3][lr] = av1.w;
    Bs[1][lq * 4 + 0][lr] = bv1.x; Bs[1][lq * 4 + 1][lr] = bv1.y;
    Bs[1][lq * 4 + 2][lr] = bv1.z; Bs[1][lq * 4 + 3][lr] = bv1.w;
    __syncthreads();

    float acc[4][4] = {};
#pragma unroll
    for (int half = 0; half < 2; half++) {
#pragma unroll
        for (int kk = 0; kk < 16; kk++) {
            float4 a  = *(const float4*)&As[half][kk][ty * 4];
            float4 bb = *(const float4*)&Bs[half][kk][tx * 4];
            float ar[4] = {a.x, a.y, a.z, a.w};
            float br[4] = {bb.x, bb.y, bb.z, bb.w};
#pragma unroll
            for (int ia = 0; ia < 4; ia++)
#pragma unroll
                for (int ib = 0; ib < 4; ib++)
                    acc[ia][ib] += ar[ia] * br[ib];
        }
    }

#pragma unroll
    for (int ia = 0; ia < 4; ia++)
#pragma unroll
        for (int ib = 0; ib < 4; ib++)
            atomicAdd(&g_S[(size_t)(m0 + ty * 4 + ia) * RP + n0 + tx * 4 + ib],
                      acc[ia][ib]);
}

// ============================================================
// K5: presence + rinv from Gram diagonal, then per-class masked
// LSE + positive mean. BRANCH-FREE inner loop: all 21 g_S loads
// issued unconditionally (absent rows have G=0 -> v=0 -> ev=1,
// always finite), accumulation predicated with ?: (adding 0.0f
// keeps sums bit-identical to the skip version). Full unroll ->
// MLP 21 instead of serialized divergent loads.
// ============================================================
__global__ __launch_bounds__(256) void k5_loss(float* __restrict__ out)
{
    __shared__ unsigned char pres[NR];
    __shared__ float rinv[NR];
    __shared__ float red0[256], red1[256], red2[256];
    int tid = threadIdx.x;
    int c = blockIdx.x;

    for (int e = tid; e < NR; e += 256) {
        int b = e / NC, cc = e - b * NC;
        int s = 0;
#pragma unroll
        for (int j = 0; j < 32; j++) s += g_cntC[b * 32 + j][cc];
        pres[e] = (s > 0) ? 1 : 0;
        float g = g_S[(size_t)e * RP + e];          // diag: in stored tile
        rinv[e] = 1.0f / fmaxf(sqrtf(g), 1e-12f);
    }
    __syncthreads();

    int i = tid >> 4, j = tid & 15;
    float s_all = 0.f, s_diag = 0.f, p_sum = 0.f;
    int r1 = i * NC + c;
    bool  m1 = (pres[r1] != 0);
    float ri = rinv[r1];

#pragma unroll
    for (int e = 0; e < NC; e++) {
        int r2 = j * NC + e;
        int src = ((r1 >> 6) >= (r2 >> 6)) ? (r1 * RP + r2)
                                           : (r2 * RP + r1);
        float g  = g_S[src];
        float v  = (g * ri * rinv[r2]) / 0.1f;
        float ev = expf(v);
        bool  m  = m1 && (pres[r2] != 0);
        s_all += m ? ev : 0.0f;
        if (e == c) {
            s_diag += m ? ev : 0.0f;
            p_sum  += m ? v  : 0.0f;
        }
    }

    red0[tid] = s_all; red1[tid] = s_diag; red2[tid] = p_sum;
    __syncthreads();
    for (int st = 128; st; st >>= 1) {
        if (tid < st) {
            red0[tid] += red0[tid + st];
            red1[tid] += red1[tid + st];
            red2[tid] += red2[tid + st];
        }
        __syncthreads();
    }
    if (tid == 0) {
        int nc = 0;
        for (int ii = 0; ii < NB; ii++) nc += pres[ii * NC + c];
        if (nc > 0) {
            float lse = logf(red1[0] + red0[0]);   // logaddexp(lse_diag, lse_all)
            float pm  = red2[0] / (float)(nc * nc);
            atomicAdd(out, lse - pm);
        }
    }
}

// ============================================================
extern "C" void kernel_launch(void* const* d_in, const int* in_sizes, int n_in,
                              void* d_out, int out_size)
{
    const float* feat   = (const float*)d_in[0];
    const int*   labels = (const int*)d_in[1];
    float*       out    = (float*)d_out;

    k1_labels<<<dim3(NB, 32), 128>>>(labels, out);
    k2_pool<<<NB * ND / 4, 128>>>(feat);
    k4_gemm<<<NTASK, 256>>>();
    k5_loss<<<NC, 256>>>(out);
}

// round 16
// speedup vs baseline: 1.1007x; 1.1007x over previous
#include <cuda_runtime.h>
#include <cstdint>

#define NB   16
#define NC   21
#define ND   512
#define HW   4096
#define NR   (NB*NC)   /* 336 */
#define RP   384
#define LABW 513
#define KSPL 16        /* K=32 per GEMM task */
#define NTRI 21        /* lower-tri 64x64 tiles of 6x6 */
#define NTASK (KSPL*NTRI)  /* 336 */

// -------- device scratch (no allocations allowed) --------
__device__ unsigned char g_lab[NB * HW];        // resized labels, u8
__device__ int           g_cntC[NB * 32][NC];   // per-chunk class counts
__device__ float         g_sums[RP * ND];       // pooled sums (rows >=336 never
                                                // written -> stay zero forever)
__device__ float         g_S[RP * RP];          // raw Gram (atomic; lower tiles)
__device__ float         g_acc[NC * 3];         // per-class {s_all, s_diag, p_sum}
__device__ int           g_done[NC];            // per-class finished-block tickets

// ============================================================
// K1: bilinear label resize (jax bilinear, antialias=False, fp32,
// H then W, truncation). Scattered independent loads (MLP 4),
// grid (16 images, 32 slabs) x 128 thr, 1 px/thread. Also zeroes
// g_S, g_acc, g_done and d_out (graph-ordered before consumers).
// ============================================================
__global__ __launch_bounds__(128) void k1_labels(const int* __restrict__ labels,
                                                 float* __restrict__ out)
{
    int b = blockIdx.x, j = blockIdx.y;
    int tid = threadIdx.x;
    __shared__ int scnt[NC];
    if (tid < NC) scnt[tid] = 0;

    // zero g_S: 36864 float4 spread over 65536 threads
    int gt = (j * NB + b) * 128 + tid;
    if (gt < RP * RP / 4)
        ((float4*)g_S)[gt] = make_float4(0.f, 0.f, 0.f, 0.f);
    if (b == 0 && j == 0) {
        if (tid < NC * 3) g_acc[tid] = 0.0f;
        if (tid >= 64 && tid < 64 + NC) g_done[tid - 64] = 0;
        if (tid == 127) out[0] = 0.0f;
    }
    __syncthreads();

    const int* lb = labels + (size_t)b * (LABW * LABW);
    int o  = j * 128 + tid;
    int oy = o >> 6, ox = o & 63;

    float sy  = __fsub_rn(__fmul_rn((float)oy + 0.5f, 8.015625f), 0.5f);
    int   y0  = (int)floorf(sy);
    float fy  = __fsub_rn(sy, (float)y0);
    float wy0 = __fsub_rn(1.0f, fy);
    float xy1 = __fsub_rn((float)(y0 + 1), sy);
    float wy1 = __fsub_rn(1.0f, xy1);
    float ty  = __fadd_rn(wy0, wy1);
    wy0 = __fdiv_rn(wy0, ty);
    wy1 = __fdiv_rn(wy1, ty);

    float sx  = __fsub_rn(__fmul_rn((float)ox + 0.5f, 8.015625f), 0.5f);
    int   x0  = (int)floorf(sx);
    float fx  = __fsub_rn(sx, (float)x0);
    float wx0 = __fsub_rn(1.0f, fx);
    float xx1 = __fsub_rn((float)(x0 + 1), sx);
    float wx1 = __fsub_rn(1.0f, xx1);
    float tx  = __fadd_rn(wx0, wx1);
    wx0 = __fdiv_rn(wx0, tx);
    wx1 = __fdiv_rn(wx1, tx);

    float v00 = (float)lb[y0 * LABW + x0];
    float v01 = (float)lb[y0 * LABW + x0 + 1];
    float v10 = (float)lb[(y0 + 1) * LABW + x0];
    float v11 = (float)lb[(y0 + 1) * LABW + x0 + 1];

    float t0 = __fadd_rn(__fmul_rn(wy0, v00), __fmul_rn(wy1, v10));
    float t1 = __fadd_rn(__fmul_rn(wy0, v01), __fmul_rn(wy1, v11));
    float v  = __fadd_rn(__fmul_rn(wx0, t0), __fmul_rn(wx1, t1));

    int li = (int)v;   // truncation toward zero (values >= 0)
    g_lab[b * HW + o] = (unsigned char)li;
    atomicAdd(&scnt[li], 1);
    __syncthreads();
    if (tid < NC) g_cntC[b * 32 + j][tid] = scnt[tid];
}

// ============================================================
// K2: masked pooling (128MB DRAM pass). 2048 blocks x 128 thr,
// FOUR d-channels per block: labels loaded ONCE into registers
// and reused across the 4 feature passes (label L2 traffic /4).
// Conflict-free smem scatter (bank = tid%32 for all classes).
// ============================================================
__global__ __launch_bounds__(128) void k2_pool(const float* __restrict__ feat)
{
    __shared__ float sacc[NC * 128];
    int tid = threadIdx.x;
    int blk = blockIdx.x;          // 128 blocks per image
    int b   = blk >> 7;
    int d0  = (blk & 127) * 4;

    const unsigned int* l4 = (const unsigned int*)g_lab + b * (HW / 4);
    unsigned int lv[8];
#pragma unroll
    for (int k = 0; k < 8; k++) lv[k] = l4[tid + 128 * k];

    for (int dd = 0; dd < 4; dd++) {
        int bd = b * ND + d0 + dd;

        float4* z4 = (float4*)sacc;
#pragma unroll
        for (int i = 0; i < 6; i++) {
            int idx = tid + 128 * i;
            if (idx < NC * 32) z4[idx] = make_float4(0.f, 0.f, 0.f, 0.f);
        }
        __syncthreads();

        const float4* f4 = (const float4*)(feat + (size_t)bd * HW);
        float4 fv[8];
#pragma unroll
        for (int k = 0; k < 8; k++) fv[k] = f4[tid + 128 * k];

#pragma unroll
        for (int k = 0; k < 8; k++) {
            unsigned int L = lv[k];
            sacc[((L      ) & 255u) * 128 + tid] += fv[k].x;
            sacc[((L >>  8) & 255u) * 128 + tid] += fv[k].y;
            sacc[((L >> 16) & 255u) * 128 + tid] += fv[k].z;
            sacc[((L >> 24) & 255u) * 128 + tid] += fv[k].w;
        }
        __syncthreads();

        int w = tid >> 5, l = tid & 31;
        for (int c = w; c < NC; c += 4) {
            const float* p = &sacc[c * 128 + l];
            float s = p[0] + p[32] + p[64] + p[96];
#pragma unroll
            for (int o = 16; o; o >>= 1) s += __shfl_xor_sync(0xffffffffu, s, o);
            if (l == 0)
                g_sums[(size_t)(b * NC + c) * ND + d0 + dd] = s;
        }
        __syncthreads();
    }
}

// ============================================================
// K4: RAW Gram (unnormalized sums), lower-tri 64x64 tiles,
// K=32 per block, ONE task per block (336 blocks, single wave),
// all 4 tile-loads prefetched, atomicAdd accumulation into g_S
// (zeroed by k1). Normalization deferred to k5 via the diagonal.
// ============================================================
__global__ __launch_bounds__(256) void k4_gemm()
{
    __shared__ float As[2][16][68];
    __shared__ float Bs[2][16][68];
    int tid = threadIdx.x;
    int bid = blockIdx.x;
    int z = bid / NTRI, t = bid - z * NTRI;

    int ti = 0;
    while ((ti + 1) * (ti + 2) / 2 <= t) ti++;
    int tj = t - ti * (ti + 1) / 2;

    int m0 = ti * 64, n0 = tj * 64, k0 = z * 32;
    int tx = tid & 15, ty = tid >> 4;
    int lr = tid >> 2, lq = tid & 3;

    const float* pa = &g_sums[(size_t)(m0 + lr) * ND + k0 + lq * 4];
    const float* pb = &g_sums[(size_t)(n0 + lr) * ND + k0 + lq * 4];
    float4 av0 = *(const float4*)pa;
    float4 bv0 = *(const float4*)pb;
    float4 av1 = *(const float4*)(pa + 16);
    float4 bv1 = *(const float4*)(pb + 16);

    As[0][lq * 4 + 0][lr] = av0.x; As[0][lq * 4 + 1][lr] = av0.y;
    As[0][lq * 4 + 2][lr] = av0.z; As[0][lq * 4 + 3][lr] = av0.w;
    Bs[0][lq * 4 + 0][lr] = bv0.x; Bs[0][lq * 4 + 1][lr] = bv0.y;
    Bs[0][lq * 4 + 2][lr] = bv0.z; Bs[0][lq * 4 + 3][lr] = bv0.w;
    As[1][lq * 4 + 0][lr] = av1.x; As[1][lq * 4 + 1][lr] = av1.y;
    As[1][lq * 4 + 2][lr] = av1.z; As[1][lq * 4 + 3][lr] = av1.w;
    Bs[1][lq * 4 + 0][lr] = bv1.x; Bs[1][lq * 4 + 1][lr] = bv1.y;
    Bs[1][lq * 4 + 2][lr] = bv1.z; Bs[1][lq * 4 + 3][lr] = bv1.w;
    __syncthreads();

    float acc[4][4] = {};
#pragma unroll
    for (int half = 0; half < 2; half++) {
#pragma unroll
        for (int kk = 0; kk < 16; kk++) {
            float4 a  = *(const float4*)&As[half][kk][ty * 4];
            float4 bb = *(const float4*)&Bs[half][kk][tx * 4];
            float ar[4] = {a.x, a.y, a.z, a.w};
            float br[4] = {bb.x, bb.y, bb.z, bb.w};
#pragma unroll
            for (int ia = 0; ia < 4; ia++)
#pragma unroll
                for (int ib = 0; ib < 4; ib++)
                    acc[ia][ib] += ar[ia] * br[ib];
        }
    }

#pragma unroll
    for (int ia = 0; ia < 4; ia++)
#pragma unroll
        for (int ib = 0; ib < 4; ib++)
            atomicAdd(&g_S[(size_t)(m0 + ty * 4 + ia) * RP + n0 + tx * 4 + ib],
                      acc[ia][ib]);
}

// ============================================================
// K5: grid (NC classes, NB i-rows) x 512 thr. Block (c,i):
//  - pres/rinv for all 336 rows (1 row/thread, parallel chipwide)
//  - one (j,e) term per thread (r2 == tid), mirror-indexed g_S,
//    late normalize via rinv, predicated accumulate
//  - block-reduce 3 partials -> atomicAdd g_acc[c]
//  - LAST of the 16 blocks of class c (ticket on g_done[c],
//    writers fence before ticket, reader atomic-reads g_acc)
//    computes log(s_diag+s_all) - pos_mean -> atomicAdd out.
// ============================================================
__global__ __launch_bounds__(512) void k5_loss(float* __restrict__ out)
{
    __shared__ unsigned char pres[NR];
    __shared__ float rinv[NR];
    __shared__ float red0[512], red1[512], red2[512];
    int tid = threadIdx.x;
    int c = blockIdx.x;
    int i = blockIdx.y;

    if (tid < NR) {
        int e = tid;
        int b = e / NC, cc = e - b * NC;
        int s = 0;
#pragma unroll
        for (int j = 0; j < 32; j++) s += g_cntC[b * 32 + j][cc];
        pres[e] = (s > 0) ? 1 : 0;
        float g = g_S[(size_t)e * RP + e];          // diag: in stored tile
        rinv[e] = 1.0f / fmaxf(sqrtf(g), 1e-12f);
    }
    __syncthreads();

    float s_all = 0.f, s_diag = 0.f, p_sum = 0.f;
    int r1 = i * NC + c;
    if (tid < NR) {
        int r2 = tid;                    // = j*NC + e
        int e  = tid % NC;
        int src = ((r1 >> 6) >= (r2 >> 6)) ? (r1 * RP + r2)
                                           : (r2 * RP + r1);
        float g  = g_S[src];
        float v  = (g * rinv[r1] * rinv[r2]) / 0.1f;
        float ev = expf(v);
        bool  m  = pres[r1] && pres[r2];
        s_all  = m ? ev : 0.0f;
        if (e == c) { s_diag = m ? ev : 0.0f; p_sum = m ? v : 0.0f; }
    }

    red0[tid] = s_all; red1[tid] = s_diag; red2[tid] = p_sum;
    __syncthreads();
    for (int st = 256; st; st >>= 1) {
        if (tid < st) {
            red0[tid] += red0[tid + st];
            red1[tid] += red1[tid + st];
            red2[tid] += red2[tid + st];
        }
        __syncthreads();
    }

    if (tid == 0) {
        atomicAdd(&g_acc[c * 3 + 0], red0[0]);
        atomicAdd(&g_acc[c * 3 + 1], red1[0]);
        atomicAdd(&g_acc[c * 3 + 2], red2[0]);
        __threadfence();
        if (atomicAdd(&g_done[c], 1) == NB - 1) {
            // last block of this class: totals are complete
            float a0 = atomicAdd(&g_acc[c * 3 + 0], 0.0f);
            float a1 = atomicAdd(&g_acc[c * 3 + 1], 0.0f);
            float a2 = atomicAdd(&g_acc[c * 3 + 2], 0.0f);
            int nc = 0;
#pragma unroll
            for (int ii = 0; ii < NB; ii++) nc += pres[ii * NC + c];
            if (nc > 0) {
                float lse = logf(a1 + a0);        // logaddexp(lse_diag, lse_all)
                float pm  = a2 / (float)(nc * nc);
                atomicAdd(out, lse - pm);
            }
        }
    }
}

// ============================================================
extern "C" void kernel_launch(void* const* d_in, const int* in_sizes, int n_in,
                              void* d_out, int out_size)
{
    const float* feat   = (const float*)d_in[0];
    const int*   labels = (const int*)d_in[1];
    float*       out    = (float*)d_out;

    k1_labels<<<dim3(NB, 32), 128>>>(labels, out);
    k2_pool<<<NB * ND / 4, 128>>>(feat);
    k4_gemm<<<NTASK, 256>>>();
    k5_loss<<<dim3(NC, NB), 512>>>(out);
}

// round 17
// speedup vs baseline: 1.1152x; 1.0132x over previous
#include <cuda_runtime.h>
#include <cstdint>

#define NB   16
#define NC   21
#define ND   512
#define HW   4096
#define NR   (NB*NC)   /* 336 */
#define RP   384
#define LABW 513
#define KSPL 16        /* K=32 per GEMM task */
#define NTRI 21        /* lower-tri 64x64 tiles of 6x6 */
#define NTASK (KSPL*NTRI)  /* 336 */

// -------- device scratch (no allocations allowed) --------
__device__ unsigned char g_lab[NB * HW];        // resized labels, u8
__device__ int           g_cntC[NB * 32][NC];   // per-chunk class counts
__device__ unsigned char g_pres[NR];            // (b,c) presence (set by k2)
__device__ float         g_sums[RP * ND];       // pooled sums (rows >=336 never
                                                // written -> stay zero forever)
__device__ float         g_S[RP * RP];          // raw Gram (atomic; lower tiles)
__device__ float         g_acc[NC * 3];         // per-class {s_all, s_diag, p_sum}
__device__ int           g_done[NC];            // per-class finished-block tickets

// ============================================================
// K1: bilinear label resize (jax bilinear, antialias=False, fp32,
// H then W, truncation). Scattered independent loads (MLP 4),
// grid (16 images, 32 slabs) x 128 thr, 1 px/thread. Also zeroes
// g_S, g_acc, g_done and d_out (graph-ordered before consumers).
// ============================================================
__global__ __launch_bounds__(128) void k1_labels(const int* __restrict__ labels,
                                                 float* __restrict__ out)
{
    int b = blockIdx.x, j = blockIdx.y;
    int tid = threadIdx.x;
    __shared__ int scnt[NC];
    if (tid < NC) scnt[tid] = 0;

    // zero g_S: 36864 float4 spread over 65536 threads
    int gt = (j * NB + b) * 128 + tid;
    if (gt < RP * RP / 4)
        ((float4*)g_S)[gt] = make_float4(0.f, 0.f, 0.f, 0.f);
    if (b == 0 && j == 0) {
        if (tid < NC * 3) g_acc[tid] = 0.0f;
        if (tid >= 64 && tid < 64 + NC) g_done[tid - 64] = 0;
        if (tid == 127) out[0] = 0.0f;
    }
    __syncthreads();

    const int* lb = labels + (size_t)b * (LABW * LABW);
    int o  = j * 128 + tid;
    int oy = o >> 6, ox = o & 63;

    float sy  = __fsub_rn(__fmul_rn((float)oy + 0.5f, 8.015625f), 0.5f);
    int   y0  = (int)floorf(sy);
    float fy  = __fsub_rn(sy, (float)y0);
    float wy0 = __fsub_rn(1.0f, fy);
    float xy1 = __fsub_rn((float)(y0 + 1), sy);
    float wy1 = __fsub_rn(1.0f, xy1);
    float ty  = __fadd_rn(wy0, wy1);
    wy0 = __fdiv_rn(wy0, ty);
    wy1 = __fdiv_rn(wy1, ty);

    float sx  = __fsub_rn(__fmul_rn((float)ox + 0.5f, 8.015625f), 0.5f);
    int   x0  = (int)floorf(sx);
    float fx  = __fsub_rn(sx, (float)x0);
    float wx0 = __fsub_rn(1.0f, fx);
    float xx1 = __fsub_rn((float)(x0 + 1), sx);
    float wx1 = __fsub_rn(1.0f, xx1);
    float tx  = __fadd_rn(wx0, wx1);
    wx0 = __fdiv_rn(wx0, tx);
    wx1 = __fdiv_rn(wx1, tx);

    float v00 = (float)lb[y0 * LABW + x0];
    float v01 = (float)lb[y0 * LABW + x0 + 1];
    float v10 = (float)lb[(y0 + 1) * LABW + x0];
    float v11 = (float)lb[(y0 + 1) * LABW + x0 + 1];

    float t0 = __fadd_rn(__fmul_rn(wy0, v00), __fmul_rn(wy1, v10));
    float t1 = __fadd_rn(__fmul_rn(wy0, v01), __fmul_rn(wy1, v11));
    float v  = __fadd_rn(__fmul_rn(wx0, t0), __fmul_rn(wx1, t1));

    int li = (int)v;   // truncation toward zero (values >= 0)
    g_lab[b * HW + o] = (unsigned char)li;
    atomicAdd(&scnt[li], 1);
    __syncthreads();
    if (tid < NC) g_cntC[b * 32 + j][tid] = scnt[tid];
}

// ============================================================
// K2: masked pooling (128MB DRAM pass). 2048 blocks x 128 thr,
// FOUR d-channels per block, labels loaded once into registers.
// Conflict-free smem scatter (bank = tid%32 for all classes).
// NEW: first 336 blocks also compute g_pres via one warp ballot
// (32 parallel g_cntC loads) — hidden under the DRAM stream.
// ============================================================
__global__ __launch_bounds__(128) void k2_pool(const float* __restrict__ feat)
{
    __shared__ float sacc[NC * 128];
    int tid = threadIdx.x;
    int blk = blockIdx.x;          // 128 blocks per image
    int b   = blk >> 7;
    int d0  = (blk & 127) * 4;

    // presence: one element per block for blk < NR (after k1, graph-ordered)
    if (blk < NR && tid < 32) {
        int bb = blk / NC, cc = blk - bb * NC;
        int s = g_cntC[bb * 32 + tid][cc];
        unsigned any = __ballot_sync(0xffffffffu, s > 0);
        if (tid == 0) g_pres[blk] = any ? 1 : 0;
    }

    const unsigned int* l4 = (const unsigned int*)g_lab + b * (HW / 4);
    unsigned int lv[8];
#pragma unroll
    for (int k = 0; k < 8; k++) lv[k] = l4[tid + 128 * k];

    for (int dd = 0; dd < 4; dd++) {
        int bd = b * ND + d0 + dd;

        float4* z4 = (float4*)sacc;
#pragma unroll
        for (int i = 0; i < 6; i++) {
            int idx = tid + 128 * i;
            if (idx < NC * 32) z4[idx] = make_float4(0.f, 0.f, 0.f, 0.f);
        }
        __syncthreads();

        const float4* f4 = (const float4*)(feat + (size_t)bd * HW);
        float4 fv[8];
#pragma unroll
        for (int k = 0; k < 8; k++) fv[k] = f4[tid + 128 * k];

#pragma unroll
        for (int k = 0; k < 8; k++) {
            unsigned int L = lv[k];
            sacc[((L      ) & 255u) * 128 + tid] += fv[k].x;
            sacc[((L >>  8) & 255u) * 128 + tid] += fv[k].y;
            sacc[((L >> 16) & 255u) * 128 + tid] += fv[k].z;
            sacc[((L >> 24) & 255u) * 128 + tid] += fv[k].w;
        }
        __syncthreads();

        int w = tid >> 5, l = tid & 31;
        for (int c = w; c < NC; c += 4) {
            const float* p = &sacc[c * 128 + l];
            float s = p[0] + p[32] + p[64] + p[96];
#pragma unroll
            for (int o = 16; o; o >>= 1) s += __shfl_xor_sync(0xffffffffu, s, o);
            if (l == 0)
                g_sums[(size_t)(b * NC + c) * ND + d0 + dd] = s;
        }
        __syncthreads();
    }
}

// ============================================================
// K4: RAW Gram (unnormalized sums), lower-tri 64x64 tiles,
// K=32 per block, ONE task per block (336 blocks, single wave),
// all 4 tile-loads prefetched, atomicAdd accumulation into g_S
// (zeroed by k1). Normalization deferred to k5 via the diagonal.
// ============================================================
__global__ __launch_bounds__(256) void k4_gemm()
{
    __shared__ float As[2][16][68];
    __shared__ float Bs[2][16][68];
    int tid = threadIdx.x;
    int bid = blockIdx.x;
    int z = bid / NTRI, t = bid - z * NTRI;

    int ti = 0;
    while ((ti + 1) * (ti + 2) / 2 <= t) ti++;
    int tj = t - ti * (ti + 1) / 2;

    int m0 = ti * 64, n0 = tj * 64, k0 = z * 32;
    int tx = tid & 15, ty = tid >> 4;
    int lr = tid >> 2, lq = tid & 3;

    const float* pa = &g_sums[(size_t)(m0 + lr) * ND + k0 + lq * 4];
    const float* pb = &g_sums[(size_t)(n0 + lr) * ND + k0 + lq * 4];
    float4 av0 = *(const float4*)pa;
    float4 bv0 = *(const float4*)pb;
    float4 av1 = *(const float4*)(pa + 16);
    float4 bv1 = *(const float4*)(pb + 16);

    As[0][lq * 4 + 0][lr] = av0.x; As[0][lq * 4 + 1][lr] = av0.y;
    As[0][lq * 4 + 2][lr] = av0.z; As[0][lq * 4 + 3][lr] = av0.w;
    Bs[0][lq * 4 + 0][lr] = bv0.x; Bs[0][lq * 4 + 1][lr] = bv0.y;
    Bs[0][lq * 4 + 2][lr] = bv0.z; Bs[0][lq * 4 + 3][lr] = bv0.w;
    As[1][lq * 4 + 0][lr] = av1.x; As[1][lq * 4 + 1][lr] = av1.y;
    As[1][lq * 4 + 2][lr] = av1.z; As[1][lq * 4 + 3][lr] = av1.w;
    Bs[1][lq * 4 + 0][lr] = bv1.x; Bs[1][lq * 4 + 1][lr] = bv1.y;
    Bs[1][lq * 4 + 2][lr] = bv1.z; Bs[1][lq * 4 + 3][lr] = bv1.w;
    __syncthreads();

    float acc[4][4] = {};
#pragma unroll
    for (int half = 0; half < 2; half++) {
#pragma unroll
        for (int kk = 0; kk < 16; kk++) {
            float4 a  = *(const float4*)&As[half][kk][ty * 4];
            float4 bb = *(const float4*)&Bs[half][kk][tx * 4];
            float ar[4] = {a.x, a.y, a.z, a.w};
            float br[4] = {bb.x, bb.y, bb.z, bb.w};
#pragma unroll
            for (int ia = 0; ia < 4; ia++)
#pragma unroll
                for (int ib = 0; ib < 4; ib++)
                    acc[ia][ib] += ar[ia] * br[ib];
        }
    }

#pragma unroll
    for (int ia = 0; ia < 4; ia++)
#pragma unroll
        for (int ib = 0; ib < 4; ib++)
            atomicAdd(&g_S[(size_t)(m0 + ty * 4 + ia) * RP + n0 + tx * 4 + ib],
                      acc[ia][ib]);
}

// ============================================================
// K5: grid (NC classes, NB i-rows) x 512 thr. Block (c,i):
//  - cheap prologue: pres from g_pres (1 byte/thread), rinv from
//    the Gram diagonal (1 load/thread)
//  - one (j,e) term per thread (r2 == tid), mirror-indexed g_S,
//    late normalize via rinv, predicated accumulate
//  - block-reduce 3 partials -> atomicAdd g_acc[c]
//  - LAST of the 16 blocks of class c (ticket on g_done[c])
//    computes log(s_diag+s_all) - pos_mean -> atomicAdd out.
// ============================================================
__global__ __launch_bounds__(512) void k5_loss(float* __restrict__ out)
{
    __shared__ unsigned char pres[NR];
    __shared__ float rinv[NR];
    __shared__ float red0[512], red1[512], red2[512];
    int tid = threadIdx.x;
    int c = blockIdx.x;
    int i = blockIdx.y;

    if (tid < NR) {
        pres[tid] = g_pres[tid];
        float g = g_S[(size_t)tid * RP + tid];      // diag: in stored tile
        rinv[tid] = 1.0f / fmaxf(sqrtf(g), 1e-12f);
    }
    __syncthreads();

    float s_all = 0.f, s_diag = 0.f, p_sum = 0.f;
    int r1 = i * NC + c;
    if (tid < NR) {
        int r2 = tid;                    // = j*NC + e
        int e  = tid % NC;
        int src = ((r1 >> 6) >= (r2 >> 6)) ? (r1 * RP + r2)
                                           : (r2 * RP + r1);
        float g  = g_S[src];
        float v  = (g * rinv[r1] * rinv[r2]) / 0.1f;
        float ev = expf(v);
        bool  m  = pres[r1] && pres[r2];
        s_all  = m ? ev : 0.0f;
        if (e == c) { s_diag = m ? ev : 0.0f; p_sum = m ? v : 0.0f; }
    }

    red0[tid] = s_all; red1[tid] = s_diag; red2[tid] = p_sum;
    __syncthreads();
    for (int st = 256; st; st >>= 1) {
        if (tid < st) {
            red0[tid] += red0[tid + st];
            red1[tid] += red1[tid + st];
            red2[tid] += red2[tid + st];
        }
        __syncthreads();
    }

    if (tid == 0) {
        atomicAdd(&g_acc[c * 3 + 0], red0[0]);
        atomicAdd(&g_acc[c * 3 + 1], red1[0]);
        atomicAdd(&g_acc[c * 3 + 2], red2[0]);
        __threadfence();
        if (atomicAdd(&g_done[c], 1) == NB - 1) {
            // last block of this class: totals are complete
            float a0 = atomicAdd(&g_acc[c * 3 + 0], 0.0f);
            float a1 = atomicAdd(&g_acc[c * 3 + 1], 0.0f);
            float a2 = atomicAdd(&g_acc[c * 3 + 2], 0.0f);
            int nc = 0;
#pragma unroll
            for (int ii = 0; ii < NB; ii++) nc += pres[ii * NC + c];
            if (nc > 0) {
                float lse = logf(a1 + a0);        // logaddexp(lse_diag, lse_all)
                float pm  = a2 / (float)(nc * nc);
                atomicAdd(out, lse - pm);
            }
        }
    }
}

// ============================================================
extern "C" void kernel_launch(void* const* d_in, const int* in_sizes, int n_in,
                              void* d_out, int out_size)
{
    const float* feat   = (const float*)d_in[0];
    const int*   labels = (const int*)d_in[1];
    float*       out    = (float*)d_out;

    k1_labels<<<dim3(NB, 32), 128>>>(labels, out);
    k2_pool<<<NB * ND / 4, 128>>>(feat);
    k4_gemm<<<NTASK, 256>>>();
    k5_loss<<<dim3(NC, NB), 512>>>(out);
}